// round 9
// baseline (speedup 1.0000x reference)
#include <cuda_runtime.h>
#include <cuda_fp16.h>
#include <math.h>

#define B_ 4
#define S_ 1024
#define D_ 1024
#define H_ 16
#define BH 64
#define MROWS 4096

// ---------------- device scratch (no allocation allowed) -------------------
__device__ __half g_xh[3][MROWS * D_];
__device__ __half g_wt[4][D_ * D_];
__device__ __half g_qh[BH * S_ * 64];
__device__ __half g_kh[BH * S_ * 64];
__device__ __half g_vh[BH * S_ * 64];
__device__ __half g_ctxh[MROWS * D_];
__device__ float  g_tmp[MROWS * D_];
__device__ float  g_attn_fb[(size_t)BH * S_ * S_];

// ---------------- helpers ---------------------------------------------------
__device__ __forceinline__ void mma16816(float* c, const unsigned* a, const unsigned* b)
{
    asm volatile(
        "mma.sync.aligned.m16n8k16.row.col.f32.f16.f16.f32 "
        "{%0,%1,%2,%3}, {%4,%5,%6,%7}, {%8,%9}, {%0,%1,%2,%3};\n"
        : "+f"(c[0]), "+f"(c[1]), "+f"(c[2]), "+f"(c[3])
        : "r"(a[0]), "r"(a[1]), "r"(a[2]), "r"(a[3]), "r"(b[0]), "r"(b[1]));
}

__device__ __forceinline__ void cp_async16(void* smem, const void* gmem)
{
    unsigned s = (unsigned)__cvta_generic_to_shared(smem);
    asm volatile("cp.async.ca.shared.global [%0], [%1], 16;\n" :: "r"(s), "l"(gmem));
}
__device__ __forceinline__ void cp_commit() { asm volatile("cp.async.commit_group;\n"); }
__device__ __forceinline__ void cp_wait0() { asm volatile("cp.async.wait_group 0;\n"); }

__device__ __forceinline__ void ldm_x2_trans(unsigned& r0, unsigned& r1, const void* smem)
{
    unsigned s = (unsigned)__cvta_generic_to_shared(smem);
    asm volatile("ldmatrix.sync.aligned.m8n8.x2.trans.shared.b16 {%0,%1}, [%2];\n"
                 : "=r"(r0), "=r"(r1) : "r"(s));
}

// FMA-only exp. |rel err| < 2e-5 on our range.
__device__ __forceinline__ float fexp(float x)
{
    x = fmaxf(x, -87.0f);
    float t = x * 1.4426950408889634f;
    float fi = floorf(t);
    float f = t - fi;
    int i = (int)fi;
    float p = 1.5403530e-4f;
    p = fmaf(p, f, 1.3333558e-3f);
    p = fmaf(p, f, 9.6181291e-3f);
    p = fmaf(p, f, 5.5504109e-2f);
    p = fmaf(p, f, 2.4022651e-1f);
    p = fmaf(p, f, 6.9314718e-1f);
    p = fmaf(p, f, 1.0f);
    return __int_as_float((i + 127) << 23) * p;
}

// ---------------- converts (merged) -----------------------------------------
__global__ __launch_bounds__(256) void cvt_x3(const float4* __restrict__ Q,
                                              const float4* __restrict__ K,
                                              const float4* __restrict__ V)
{
    const int z = blockIdx.y;
    const float4* src = (z == 0) ? Q : (z == 1) ? K : V;
    __half* dst = g_xh[z];
    int i = blockIdx.x * 256 + threadIdx.x;
    float4 v = src[i];
    __half2 h0 = __floats2half2_rn(v.x, v.y);
    __half2 h1 = __floats2half2_rn(v.z, v.w);
    uint2 o;
    o.x = *reinterpret_cast<unsigned*>(&h0);
    o.y = *reinterpret_cast<unsigned*>(&h1);
    *reinterpret_cast<uint2*>(dst + 4 * (size_t)i) = o;
}

__global__ void cvt_wt4(const float* __restrict__ W0, const float* __restrict__ W1,
                        const float* __restrict__ W2, const float* __restrict__ W3)
{
    __shared__ float t[32][33];
    const int z = blockIdx.z;
    const float* W = (z == 0) ? W0 : (z == 1) ? W1 : (z == 2) ? W2 : W3;
    __half* Wt = g_wt[z];
    const int bx = blockIdx.x * 32;
    const int by = blockIdx.y * 32;
    const int tx = threadIdx.x, ty = threadIdx.y;
    for (int dy = 0; dy < 32; dy += 8)
        t[ty + dy][tx] = W[(size_t)(by + ty + dy) * 1024 + bx + tx];
    __syncthreads();
    for (int dy = 0; dy < 32; dy += 8)
        Wt[(size_t)(bx + ty + dy) * 1024 + by + tx] = __float2half_rn(t[tx][ty + dy]);
}

// ---------------- fp16 GEMM: cp.async 2-stage, single-sync loop -------------
__global__ __launch_bounds__(256) void proj_h(const float* __restrict__ b0,
                                              const float* __restrict__ b1,
                                              const float* __restrict__ b2, int mode)
{
    __shared__ __align__(16) __half As[2][128][40];
    __shared__ __align__(16) __half Bs[2][128][40];
    const int z = (mode < 0) ? blockIdx.z : 3;
    const __half* A = (z == 3) ? g_ctxh : g_xh[z];
    const __half* Bt = g_wt[z];
    const float* bias = (z == 1) ? b1 : (z == 2) ? b2 : b0;

    const int bm = blockIdx.y * 128, bn = blockIdx.x * 128;
    const int tid = threadIdx.x, lane = tid & 31, wid = tid >> 5;
    const int wm = (wid >> 1) * 32, wn = (wid & 1) * 64;
    const int sr = tid >> 1, sc = (tid & 1) * 16;

    float acc[2][8][4];
#pragma unroll
    for (int i = 0; i < 2; i++)
#pragma unroll
        for (int j = 0; j < 8; j++)
#pragma unroll
            for (int q = 0; q < 4; q++) acc[i][j][q] = 0.f;

    const __half* arow = A + (size_t)(bm + sr) * 1024 + sc;
    const __half* brow = Bt + (size_t)(bn + sr) * 1024 + sc;

    cp_async16(&As[0][sr][sc], arow);
    cp_async16(&As[0][sr][sc + 8], arow + 8);
    cp_async16(&Bs[0][sr][sc], brow);
    cp_async16(&Bs[0][sr][sc + 8], brow + 8);
    cp_commit();

    for (int it = 0; it < 32; it++) {
        cp_wait0();
        __syncthreads();
        if (it + 1 < 32) {
            const int k0 = (it + 1) * 32;
            const int st2 = (it + 1) & 1;
            cp_async16(&As[st2][sr][sc], arow + k0);
            cp_async16(&As[st2][sr][sc + 8], arow + k0 + 8);
            cp_async16(&Bs[st2][sr][sc], brow + k0);
            cp_async16(&Bs[st2][sr][sc + 8], brow + k0 + 8);
            cp_commit();
        }
        const int st = it & 1;
#pragma unroll
        for (int ks = 0; ks < 32; ks += 16) {
            unsigned af[2][4], bf[8][2];
            const int c = ks + 2 * (lane & 3);
#pragma unroll
            for (int i = 0; i < 2; i++) {
                const int r = wm + 16 * i + (lane >> 2);
                af[i][0] = *(const unsigned*)&As[st][r][c];
                af[i][1] = *(const unsigned*)&As[st][r + 8][c];
                af[i][2] = *(const unsigned*)&As[st][r][c + 8];
                af[i][3] = *(const unsigned*)&As[st][r + 8][c + 8];
            }
#pragma unroll
            for (int j = 0; j < 8; j++) {
                const int n = wn + 8 * j + (lane >> 2);
                bf[j][0] = *(const unsigned*)&Bs[st][n][c];
                bf[j][1] = *(const unsigned*)&Bs[st][n][c + 8];
            }
#pragma unroll
            for (int i = 0; i < 2; i++)
#pragma unroll
                for (int j = 0; j < 8; j++)
                    mma16816(acc[i][j], af[i], bf[j]);
        }
    }

#pragma unroll
    for (int i = 0; i < 2; i++) {
        const int r0 = bm + wm + 16 * i + (lane >> 2);
#pragma unroll
        for (int j = 0; j < 8; j++) {
            const int n0 = bn + wn + 8 * j + 2 * (lane & 3);
            const float bb0 = bias[n0], bb1 = bias[n0 + 1];
            const float l0 = acc[i][j][0] + bb0, l1 = acc[i][j][1] + bb1;
            const float h0 = acc[i][j][2] + bb0, h1 = acc[i][j][3] + bb1;
            if (z == 3) {
                *(float2*)&g_tmp[(size_t)r0 * 1024 + n0] = make_float2(l0, l1);
                *(float2*)&g_tmp[(size_t)(r0 + 8) * 1024 + n0] = make_float2(h0, h1);
            } else {
                __half* dst = (z == 0) ? g_qh : (z == 1) ? g_kh : g_vh;
                const int bat = r0 >> 10, s = r0 & 1023, h = n0 >> 6, d = n0 & 63;
                __half2 lo = __floats2half2_rn(l0, l1);
                __half2 hi = __floats2half2_rn(h0, h1);
                *(__half2*)&dst[(((size_t)(bat * 16 + h) * 1024) + s) * 64 + d] = lo;
                *(__half2*)&dst[(((size_t)(bat * 16 + h) * 1024) + s + 8) * 64 + d] = hi;
            }
        }
    }
}

// ---------------- fused attention (hoisted A-frags, wide mask loads) --------
__global__ __launch_bounds__(256) void attn_kernel(const unsigned char* __restrict__ mask,
                                                   float* __restrict__ attn)
{
    __shared__ __align__(16) __half Aq[16][88];
    __shared__ __align__(16) __half KV[2][128][88];
    __shared__ float rsum[16][8];
    __shared__ float rinv[16];
    float (*cpart)[16][64] = (float(*)[16][64])KV;   // phase-4 overlay

    const int bh = blockIdx.y;
    const int qb = blockIdx.x * 16;
    const int tid = threadIdx.x, lane = tid & 31, wid = tid >> 5;
    const int bat = bh >> 4;
    const int q2 = 2 * (lane & 3);

    const __half* qp = g_qh + (size_t)bh * 65536;
    const __half* kp = g_kh + (size_t)bh * 65536;
    const __half* vp = g_vh + (size_t)bh * 65536;

    {
        const int r = tid >> 4, c = (tid & 15) * 4;
        *(uint2*)&Aq[r][c] = *(const uint2*)&qp[(size_t)(qb + r) * 64 + c];
    }

    const int lr = tid >> 1, lc = (tid & 1) * 32;
#define LOADKV(PTR, CH, ST) { \
        const __half* s_ = (PTR) + (size_t)((CH) * 128 + lr) * 64 + lc; \
        cp_async16(&KV[ST][lr][lc], s_); \
        cp_async16(&KV[ST][lr][lc + 8], s_ + 8); \
        cp_async16(&KV[ST][lr][lc + 16], s_ + 16); \
        cp_async16(&KV[ST][lr][lc + 24], s_ + 24); \
        cp_commit(); }

    LOADKV(kp, 0, 0);
    __syncthreads();                        // Aq tile visible

    // ---- hoist Q A-fragments into registers (loaded ONCE) ----
    unsigned af[4][4];
    {
        const int r = lane >> 2;
#pragma unroll
        for (int k4 = 0; k4 < 4; k4++) {
            const int c = k4 * 16 + q2;
            af[k4][0] = *(const unsigned*)&Aq[r][c];
            af[k4][1] = *(const unsigned*)&Aq[r + 8][c];
            af[k4][2] = *(const unsigned*)&Aq[r][c + 8];
            af[k4][3] = *(const unsigned*)&Aq[r + 8][c + 8];
        }
    }

    // ---- phase 1: scores (K pipelined) ----
    float p[16][4];
#pragma unroll
    for (int t = 0; t < 16; t++)
#pragma unroll
        for (int q = 0; q < 4; q++) p[t][q] = 0.f;

#pragma unroll
    for (int ch = 0; ch < 8; ch++) {
        cp_wait0();
        __syncthreads();
        if (ch < 7) LOADKV(kp, ch + 1, (ch + 1) & 1);
        const int st = ch & 1;
#pragma unroll
        for (int k4 = 0; k4 < 4; k4++) {
            const int c = k4 * 16 + q2;
#pragma unroll
            for (int j = 0; j < 2; j++) {
                const int n = wid * 16 + 8 * j + (lane >> 2);
                unsigned bf[2];
                bf[0] = *(const unsigned*)&KV[st][n][c];
                bf[1] = *(const unsigned*)&KV[st][n][c + 8];
                mma16816(p[2 * ch + j], af[k4], bf);
            }
        }
    }

    // ---- phase 2: mask (wide loads) + scale + exp + row sums + pack ----
    const unsigned char* mb = mask + ((size_t)bat << 20);
    const int r0g = qb + (lane >> 2);
    const int sh = 16 * (lane & 3);
    float s0 = 0.f, s1 = 0.f;
    unsigned ph[8][4];
#pragma unroll
    for (int ch = 0; ch < 8; ch++) {
        const int colb = ch * 128 + wid * 16;
        uint4 m0 = *(const uint4*)(mb + ((size_t)r0g << 10) + colb);
        uint4 m1 = *(const uint4*)(mb + ((size_t)(r0g + 8) << 10) + colb);
        unsigned long long lo0 = m0.x | ((unsigned long long)m0.y << 32);
        unsigned long long hi0 = m0.z | ((unsigned long long)m0.w << 32);
        unsigned long long lo1 = m1.x | ((unsigned long long)m1.y << 32);
        unsigned long long hi1 = m1.z | ((unsigned long long)m1.w << 32);
#pragma unroll
        for (int j = 0; j < 2; j++) {
            const int t = 2 * ch + j;
            const unsigned long long w0 = j ? hi0 : lo0;
            const unsigned long long w1 = j ? hi1 : lo1;
            float v0 = ((w0 >> sh) & 0xffull) ? -1e9f : p[t][0] * 0.125f;
            float v1 = ((w0 >> (sh + 8)) & 0xffull) ? -1e9f : p[t][1] * 0.125f;
            float v2 = ((w1 >> sh) & 0xffull) ? -1e9f : p[t][2] * 0.125f;
            float v3 = ((w1 >> (sh + 8)) & 0xffull) ? -1e9f : p[t][3] * 0.125f;
            v0 = fexp(v0); v1 = fexp(v1); v2 = fexp(v2); v3 = fexp(v3);
            s0 += v0 + v1; s1 += v2 + v3;
            __half2 x0 = __floats2half2_rn(v0, v1);
            __half2 x1 = __floats2half2_rn(v2, v3);
            ph[ch][2 * j + 0] = *reinterpret_cast<unsigned*>(&x0);
            ph[ch][2 * j + 1] = *reinterpret_cast<unsigned*>(&x1);
        }
    }
    s0 += __shfl_xor_sync(0xffffffffu, s0, 1);
    s0 += __shfl_xor_sync(0xffffffffu, s0, 2);
    s1 += __shfl_xor_sync(0xffffffffu, s1, 1);
    s1 += __shfl_xor_sync(0xffffffffu, s1, 2);
    if ((lane & 3) == 0) {
        rsum[lane >> 2][wid] = s0;
        rsum[8 + (lane >> 2)][wid] = s1;
    }
    __syncthreads();

    LOADKV(vp, 0, 0);   // prefetch V chunk 0 during normalization

    if (tid < 16) {
        float t = 0.f;
#pragma unroll
        for (int w = 0; w < 8; w++) t += rsum[tid][w];
        rinv[tid] = 1.f / t;
    }
    __syncthreads();
    const float inv0 = rinv[lane >> 2], inv1 = rinv[8 + (lane >> 2)];

    // ---- phase 2b: stream attn (fp32 from packed halves) ----
    float* ab = attn + ((size_t)bh << 20);
#pragma unroll
    for (int ch = 0; ch < 8; ch++) {
#pragma unroll
        for (int j = 0; j < 2; j++) {
            float2 f0 = __half22float2(*(__half2*)&ph[ch][2 * j + 0]);
            float2 f1 = __half22float2(*(__half2*)&ph[ch][2 * j + 1]);
            const int col = ch * 128 + wid * 16 + j * 8 + q2;
            __stcs((float2*)&ab[((size_t)r0g << 10) + col],
                   make_float2(f0.x * inv0, f0.y * inv0));
            __stcs((float2*)&ab[((size_t)(r0g + 8) << 10) + col],
                   make_float2(f1.x * inv1, f1.y * inv1));
        }
    }

    // ---- phase 3: ctx = attn @ V (A-frags from ph * inv, half2) ----
    const __half2 hinv0 = __float2half2_rn(inv0);
    const __half2 hinv1 = __float2half2_rn(inv1);
    float cacc[8][4];
#pragma unroll
    for (int j = 0; j < 8; j++)
#pragma unroll
        for (int q = 0; q < 4; q++) cacc[j][q] = 0.f;

#pragma unroll
    for (int ch = 0; ch < 8; ch++) {
        cp_wait0();
        __syncthreads();
        if (ch < 7) LOADKV(vp, ch + 1, (ch + 1) & 1);
        const int st = ch & 1;
        const int krow = wid * 16 + (lane & 15);
        unsigned a4[4];
        *(__half2*)&a4[0] = __hmul2(*(__half2*)&ph[ch][0], hinv0);
        *(__half2*)&a4[1] = __hmul2(*(__half2*)&ph[ch][1], hinv1);
        *(__half2*)&a4[2] = __hmul2(*(__half2*)&ph[ch][2], hinv0);
        *(__half2*)&a4[3] = __hmul2(*(__half2*)&ph[ch][3], hinv1);
#pragma unroll
        for (int j = 0; j < 8; j++) {
            unsigned b[2];
            ldm_x2_trans(b[0], b[1], &KV[st][krow][8 * j]);
            mma16816(cacc[j], a4, b);
        }
    }
    __syncthreads();   // protect KV overlay before cpart writes

    // ---- phase 4: cross-warp reduce, write ctx fp16 ----
#pragma unroll
    for (int j = 0; j < 8; j++) {
        const int n = 8 * j + q2;
        const int r = lane >> 2;
        *(float2*)&cpart[wid][r][n] = make_float2(cacc[j][0], cacc[j][1]);
        *(float2*)&cpart[wid][r + 8][n] = make_float2(cacc[j][2], cacc[j][3]);
    }
    __syncthreads();
    {
        const int r = tid >> 4, d = (tid & 15) * 4;
        float4 s = make_float4(0.f, 0.f, 0.f, 0.f);
#pragma unroll
        for (int w = 0; w < 8; w++) {
            float4 v = *(const float4*)&cpart[w][r][d];
            s.x += v.x; s.y += v.y; s.z += v.z; s.w += v.w;
        }
        const int m = (bat << 10) + qb + r;
        const int h = bh & 15;
        __half2 h0 = __floats2half2_rn(s.x, s.y);
        __half2 h1 = __floats2half2_rn(s.z, s.w);
        uint2 o;
        o.x = *reinterpret_cast<unsigned*>(&h0);
        o.y = *reinterpret_cast<unsigned*>(&h1);
        *(uint2*)&g_ctxh[(size_t)m * 1024 + (h << 6) + d] = o;
    }
#undef LOADKV
}

// ---------------- LayerNorm(residual + g_tmp) -------------------------------
__global__ __launch_bounds__(256) void ln_kernel(const float* __restrict__ resid,
                                                 const float* __restrict__ gam,
                                                 const float* __restrict__ bet,
                                                 float* __restrict__ out)
{
    __shared__ float r1[256];
    __shared__ float r2[256];
    const int row = blockIdx.x;
    const int t = threadIdx.x;
    float4 x = *(const float4*)&g_tmp[((size_t)row << 10) + t * 4];
    float4 rr = *(const float4*)&resid[((size_t)row << 10) + t * 4];
    x.x += rr.x; x.y += rr.y; x.z += rr.z; x.w += rr.w;
    r1[t] = x.x + x.y + x.z + x.w;
    r2[t] = x.x * x.x + x.y * x.y + x.z * x.z + x.w * x.w;
    __syncthreads();
    for (int s = 128; s > 0; s >>= 1) {
        if (t < s) { r1[t] += r1[t + s]; r2[t] += r2[t + s]; }
        __syncthreads();
    }
    const float mu = r1[0] * (1.f / 1024.f);
    const float var = r2[0] * (1.f / 1024.f) - mu * mu;
    const float rs = rsqrtf(var + 1e-5f);
    float4 gv = *(const float4*)&gam[t * 4];
    float4 bv = *(const float4*)&bet[t * 4];
    float4 o;
    o.x = (x.x - mu) * rs * gv.x + bv.x;
    o.y = (x.y - mu) * rs * gv.y + bv.y;
    o.z = (x.z - mu) * rs * gv.z + bv.z;
    o.w = (x.w - mu) * rs * gv.w + bv.w;
    *(float4*)&out[((size_t)row << 10) + t * 4] = o;
}

// ---------------------------------------------------------------------------
extern "C" void kernel_launch(void* const* d_in, const int* in_sizes, int n_in,
                              void* d_out, int out_size)
{
    const float* Q = (const float*)d_in[0];
    const float* K = (const float*)d_in[1];
    const float* V = (const float*)d_in[2];
    const unsigned char* mask = (const unsigned char*)d_in[3];
    const float* bq = (const float*)d_in[5];
    const float* bk = (const float*)d_in[7];
    const float* bv = (const float*)d_in[9];
    const float* bout = (const float*)d_in[11];
    const float* ln_g = (const float*)d_in[12];
    const float* ln_b = (const float*)d_in[13];
    float* out = (float*)d_out;

    const long long OUT_ELEMS = 4LL * 1024 * 1024;
    const long long ATTN_ELEMS = 64LL * 1024 * 1024;
    float* attn;
    if ((long long)out_size >= OUT_ELEMS + ATTN_ELEMS) {
        attn = out + OUT_ELEMS;
    } else {
        void* p = nullptr;
        cudaGetSymbolAddress(&p, g_attn_fb);
        attn = (float*)p;
    }

    cvt_x3<<<dim3(4096, 3), 256>>>((const float4*)Q, (const float4*)K, (const float4*)V);
    cvt_wt4<<<dim3(32, 32, 4), dim3(32, 8)>>>((const float*)d_in[4], (const float*)d_in[6],
                                              (const float*)d_in[8], (const float*)d_in[10]);

    proj_h<<<dim3(8, 32, 3), 256>>>(bq, bk, bv, -1);

    attn_kernel<<<dim3(64, 64), 256>>>(mask, attn);

    proj_h<<<dim3(8, 32), 256>>>(bout, bout, bout, 3);
    ln_kernel<<<4096, 256>>>(Q, ln_g, ln_b, out);
}

// round 12
// speedup vs baseline: 1.5211x; 1.5211x over previous
#include <cuda_runtime.h>
#include <cuda_fp16.h>
#include <math.h>

#define B_ 4
#define S_ 1024
#define D_ 1024
#define H_ 16
#define BH 64
#define MROWS 4096

// ---------------- device scratch (no allocation allowed) -------------------
__device__ __half g_xh[3][MROWS * D_];
__device__ __half g_wt[4][D_ * D_];
__device__ __half g_qh[BH * S_ * 64];
__device__ __half g_kh[BH * S_ * 64];
__device__ __half g_vh[BH * S_ * 64];
__device__ __half g_ctxh[MROWS * D_];
__device__ float  g_tmp[MROWS * D_];
__device__ float  g_attn_fb[(size_t)BH * S_ * S_];

// ---------------- helpers ---------------------------------------------------
__device__ __forceinline__ void mma16816(float* c, const unsigned* a, const unsigned* b)
{
    asm volatile(
        "mma.sync.aligned.m16n8k16.row.col.f32.f16.f16.f32 "
        "{%0,%1,%2,%3}, {%4,%5,%6,%7}, {%8,%9}, {%0,%1,%2,%3};\n"
        : "+f"(c[0]), "+f"(c[1]), "+f"(c[2]), "+f"(c[3])
        : "r"(a[0]), "r"(a[1]), "r"(a[2]), "r"(a[3]), "r"(b[0]), "r"(b[1]));
}

__device__ __forceinline__ void cp_async16(void* smem, const void* gmem)
{
    unsigned s = (unsigned)__cvta_generic_to_shared(smem);
    asm volatile("cp.async.ca.shared.global [%0], [%1], 16;\n" :: "r"(s), "l"(gmem));
}
__device__ __forceinline__ void cp_commit() { asm volatile("cp.async.commit_group;\n"); }
__device__ __forceinline__ void cp_wait0() { asm volatile("cp.async.wait_group 0;\n"); }

__device__ __forceinline__ void ldm_x2_trans(unsigned& r0, unsigned& r1, const void* smem)
{
    unsigned s = (unsigned)__cvta_generic_to_shared(smem);
    asm volatile("ldmatrix.sync.aligned.m8n8.x2.trans.shared.b16 {%0,%1}, [%2];\n"
                 : "=r"(r0), "=r"(r1) : "r"(s));
}

// FMA-only exp. |rel err| < 2e-5 on our range.
__device__ __forceinline__ float fexp(float x)
{
    x = fmaxf(x, -87.0f);
    float t = x * 1.4426950408889634f;
    float fi = floorf(t);
    float f = t - fi;
    int i = (int)fi;
    float p = 1.5403530e-4f;
    p = fmaf(p, f, 1.3333558e-3f);
    p = fmaf(p, f, 9.6181291e-3f);
    p = fmaf(p, f, 5.5504109e-2f);
    p = fmaf(p, f, 2.4022651e-1f);
    p = fmaf(p, f, 6.9314718e-1f);
    p = fmaf(p, f, 1.0f);
    return __int_as_float((i + 127) << 23) * p;
}

// ---------------- converts (merged) -----------------------------------------
__global__ __launch_bounds__(256) void cvt_x3(const float4* __restrict__ Q,
                                              const float4* __restrict__ K,
                                              const float4* __restrict__ V)
{
    const int z = blockIdx.y;
    const float4* src = (z == 0) ? Q : (z == 1) ? K : V;
    __half* dst = g_xh[z];
    int i = blockIdx.x * 256 + threadIdx.x;
    float4 v = src[i];
    __half2 h0 = __floats2half2_rn(v.x, v.y);
    __half2 h1 = __floats2half2_rn(v.z, v.w);
    uint2 o;
    o.x = *reinterpret_cast<unsigned*>(&h0);
    o.y = *reinterpret_cast<unsigned*>(&h1);
    *reinterpret_cast<uint2*>(dst + 4 * (size_t)i) = o;
}

__global__ void cvt_wt4(const float* __restrict__ W0, const float* __restrict__ W1,
                        const float* __restrict__ W2, const float* __restrict__ W3)
{
    __shared__ float t[32][33];
    const int z = blockIdx.z;
    const float* W = (z == 0) ? W0 : (z == 1) ? W1 : (z == 2) ? W2 : W3;
    __half* Wt = g_wt[z];
    const int bx = blockIdx.x * 32;
    const int by = blockIdx.y * 32;
    const int tx = threadIdx.x, ty = threadIdx.y;
    for (int dy = 0; dy < 32; dy += 8)
        t[ty + dy][tx] = W[(size_t)(by + ty + dy) * 1024 + bx + tx];
    __syncthreads();
    for (int dy = 0; dy < 32; dy += 8)
        Wt[(size_t)(bx + ty + dy) * 1024 + by + tx] = __float2half_rn(t[tx][ty + dy]);
}

// ---------------- fp16 GEMM: cp.async 2-stage, single-sync loop -------------
__global__ __launch_bounds__(256) void proj_h(const float* __restrict__ b0,
                                              const float* __restrict__ b1,
                                              const float* __restrict__ b2, int mode)
{
    __shared__ __align__(16) __half As[2][128][40];
    __shared__ __align__(16) __half Bs[2][128][40];
    const int z = (mode < 0) ? blockIdx.z : 3;
    const __half* A = (z == 3) ? g_ctxh : g_xh[z];
    const __half* Bt = g_wt[z];
    const float* bias = (z == 1) ? b1 : (z == 2) ? b2 : b0;

    const int bm = blockIdx.y * 128, bn = blockIdx.x * 128;
    const int tid = threadIdx.x, lane = tid & 31, wid = tid >> 5;
    const int wm = (wid >> 1) * 32, wn = (wid & 1) * 64;
    const int sr = tid >> 1, sc = (tid & 1) * 16;

    float acc[2][8][4];
#pragma unroll
    for (int i = 0; i < 2; i++)
#pragma unroll
        for (int j = 0; j < 8; j++)
#pragma unroll
            for (int q = 0; q < 4; q++) acc[i][j][q] = 0.f;

    const __half* arow = A + (size_t)(bm + sr) * 1024 + sc;
    const __half* brow = Bt + (size_t)(bn + sr) * 1024 + sc;

    cp_async16(&As[0][sr][sc], arow);
    cp_async16(&As[0][sr][sc + 8], arow + 8);
    cp_async16(&Bs[0][sr][sc], brow);
    cp_async16(&Bs[0][sr][sc + 8], brow + 8);
    cp_commit();

    for (int it = 0; it < 32; it++) {
        cp_wait0();
        __syncthreads();
        if (it + 1 < 32) {
            const int k0 = (it + 1) * 32;
            const int st2 = (it + 1) & 1;
            cp_async16(&As[st2][sr][sc], arow + k0);
            cp_async16(&As[st2][sr][sc + 8], arow + k0 + 8);
            cp_async16(&Bs[st2][sr][sc], brow + k0);
            cp_async16(&Bs[st2][sr][sc + 8], brow + k0 + 8);
            cp_commit();
        }
        const int st = it & 1;
#pragma unroll
        for (int ks = 0; ks < 32; ks += 16) {
            unsigned af[2][4], bf[8][2];
            const int c = ks + 2 * (lane & 3);
#pragma unroll
            for (int i = 0; i < 2; i++) {
                const int r = wm + 16 * i + (lane >> 2);
                af[i][0] = *(const unsigned*)&As[st][r][c];
                af[i][1] = *(const unsigned*)&As[st][r + 8][c];
                af[i][2] = *(const unsigned*)&As[st][r][c + 8];
                af[i][3] = *(const unsigned*)&As[st][r + 8][c + 8];
            }
#pragma unroll
            for (int j = 0; j < 8; j++) {
                const int n = wn + 8 * j + (lane >> 2);
                bf[j][0] = *(const unsigned*)&Bs[st][n][c];
                bf[j][1] = *(const unsigned*)&Bs[st][n][c + 8];
            }
#pragma unroll
            for (int i = 0; i < 2; i++)
#pragma unroll
                for (int j = 0; j < 8; j++)
                    mma16816(acc[i][j], af[i], bf[j]);
        }
    }

#pragma unroll
    for (int i = 0; i < 2; i++) {
        const int r0 = bm + wm + 16 * i + (lane >> 2);
#pragma unroll
        for (int j = 0; j < 8; j++) {
            const int n0 = bn + wn + 8 * j + 2 * (lane & 3);
            const float bb0 = bias[n0], bb1 = bias[n0 + 1];
            const float l0 = acc[i][j][0] + bb0, l1 = acc[i][j][1] + bb1;
            const float h0 = acc[i][j][2] + bb0, h1 = acc[i][j][3] + bb1;
            if (z == 3) {
                *(float2*)&g_tmp[(size_t)r0 * 1024 + n0] = make_float2(l0, l1);
                *(float2*)&g_tmp[(size_t)(r0 + 8) * 1024 + n0] = make_float2(h0, h1);
            } else {
                __half* dst = (z == 0) ? g_qh : (z == 1) ? g_kh : g_vh;
                const int bat = r0 >> 10, s = r0 & 1023, h = n0 >> 6, d = n0 & 63;
                __half2 lo = __floats2half2_rn(l0, l1);
                __half2 hi = __floats2half2_rn(h0, h1);
                *(__half2*)&dst[(((size_t)(bat * 16 + h) * 1024) + s) * 64 + d] = lo;
                *(__half2*)&dst[(((size_t)(bat * 16 + h) * 1024) + s + 8) * 64 + d] = hi;
            }
        }
    }
}

// ---------------- fused attention (R8 structure, Aq stride 88) --------------
__global__ __launch_bounds__(256) void attn_kernel(const unsigned char* __restrict__ mask,
                                                   float* __restrict__ attn)
{
    __shared__ __align__(16) __half Aq[16][88];   // stride 88: conflict-free af loads
    __shared__ __align__(16) __half KV[2][128][88];
    __shared__ float rsum[16][8];
    __shared__ float rinv[16];
    float (*cpart)[16][64] = (float(*)[16][64])KV;   // phase-4 overlay

    const int bh = blockIdx.y;
    const int qb = blockIdx.x * 16;
    const int tid = threadIdx.x, lane = tid & 31, wid = tid >> 5;
    const int bat = bh >> 4;

    const __half* qp = g_qh + (size_t)bh * 65536;
    const __half* kp = g_kh + (size_t)bh * 65536;
    const __half* vp = g_vh + (size_t)bh * 65536;

    {
        const int r = tid >> 4, c = (tid & 15) * 4;
        *(uint2*)&Aq[r][c] = *(const uint2*)&qp[(size_t)(qb + r) * 64 + c];
    }

    const int lr = tid >> 1, lc = (tid & 1) * 32;
#define LOADKV(PTR, CH, ST) { \
        const __half* s_ = (PTR) + (size_t)((CH) * 128 + lr) * 64 + lc; \
        cp_async16(&KV[ST][lr][lc], s_); \
        cp_async16(&KV[ST][lr][lc + 8], s_ + 8); \
        cp_async16(&KV[ST][lr][lc + 16], s_ + 16); \
        cp_async16(&KV[ST][lr][lc + 24], s_ + 24); \
        cp_commit(); }

    // ---- phase 1: scores (K pipelined, manual LDS frags) ----
    LOADKV(kp, 0, 0);
    float p[16][4];
#pragma unroll
    for (int t = 0; t < 16; t++)
#pragma unroll
        for (int q = 0; q < 4; q++) p[t][q] = 0.f;

    for (int ch = 0; ch < 8; ch++) {
        cp_wait0();
        __syncthreads();
        if (ch < 7) LOADKV(kp, ch + 1, (ch + 1) & 1);
        const int st = ch & 1;
#pragma unroll
        for (int ks = 0; ks < 64; ks += 16) {
            unsigned af[4];
            const int r = lane >> 2, c = ks + 2 * (lane & 3);
            af[0] = *(const unsigned*)&Aq[r][c];
            af[1] = *(const unsigned*)&Aq[r + 8][c];
            af[2] = *(const unsigned*)&Aq[r][c + 8];
            af[3] = *(const unsigned*)&Aq[r + 8][c + 8];
#pragma unroll
            for (int j = 0; j < 2; j++) {
                const int n = wid * 16 + 8 * j + (lane >> 2);
                unsigned bf[2];
                bf[0] = *(const unsigned*)&KV[st][n][c];
                bf[1] = *(const unsigned*)&KV[st][n][c + 8];
                mma16816(p[2 * ch + j], af, bf);
            }
        }
    }

    // ---- phase 2: mask + scale + exp + row sums ----
    const unsigned char* mb = mask + ((size_t)bat << 20);
    const int r0g = qb + (lane >> 2);
    float s0 = 0.f, s1 = 0.f;
#pragma unroll
    for (int t = 0; t < 16; t++) {
        const int col = (t >> 1) * 128 + wid * 16 + (t & 1) * 8 + 2 * (lane & 3);
        uchar2 m0 = *(const uchar2*)(mb + ((size_t)r0g << 10) + col);
        uchar2 m1 = *(const uchar2*)(mb + ((size_t)(r0g + 8) << 10) + col);
        float v0 = m0.x ? -1e9f : p[t][0] * 0.125f;
        float v1 = m0.y ? -1e9f : p[t][1] * 0.125f;
        float v2 = m1.x ? -1e9f : p[t][2] * 0.125f;
        float v3 = m1.y ? -1e9f : p[t][3] * 0.125f;
        v0 = fexp(v0); v1 = fexp(v1); v2 = fexp(v2); v3 = fexp(v3);
        p[t][0] = v0; p[t][1] = v1; p[t][2] = v2; p[t][3] = v3;
        s0 += v0 + v1; s1 += v2 + v3;
    }
    s0 += __shfl_xor_sync(0xffffffffu, s0, 1);
    s0 += __shfl_xor_sync(0xffffffffu, s0, 2);
    s1 += __shfl_xor_sync(0xffffffffu, s1, 1);
    s1 += __shfl_xor_sync(0xffffffffu, s1, 2);
    if ((lane & 3) == 0) {
        rsum[lane >> 2][wid] = s0;
        rsum[8 + (lane >> 2)][wid] = s1;
    }
    __syncthreads();

    LOADKV(vp, 0, 0);   // prefetch V chunk 0 during normalization

    if (tid < 16) {
        float t = 0.f;
#pragma unroll
        for (int w = 0; w < 8; w++) t += rsum[tid][w];
        rinv[tid] = 1.f / t;
    }
    __syncthreads();
    const float inv0 = rinv[lane >> 2], inv1 = rinv[8 + (lane >> 2)];

    // ---- phase 2b: normalize, stream attn, pack fp16 A-frags ----
    float* ab = attn + ((size_t)bh << 20);
    unsigned aw[8][4];
#pragma unroll
    for (int ch = 0; ch < 8; ch++) {
#pragma unroll
        for (int j = 0; j < 2; j++) {
            const int t = 2 * ch + j;
            const float n0 = p[t][0] * inv0, n1 = p[t][1] * inv0;
            const float n2 = p[t][2] * inv1, n3 = p[t][3] * inv1;
            const int col = ch * 128 + wid * 16 + j * 8 + 2 * (lane & 3);
            __stcs((float2*)&ab[((size_t)r0g << 10) + col], make_float2(n0, n1));
            __stcs((float2*)&ab[((size_t)(r0g + 8) << 10) + col], make_float2(n2, n3));
            __half2 x0 = __floats2half2_rn(n0, n1);
            __half2 x1 = __floats2half2_rn(n2, n3);
            aw[ch][2 * j + 0] = *reinterpret_cast<unsigned*>(&x0);
            aw[ch][2 * j + 1] = *reinterpret_cast<unsigned*>(&x1);
        }
    }

    // ---- phase 3: ctx = attn @ V (ldmatrix.trans B-frags) ----
    float cacc[8][4];
#pragma unroll
    for (int j = 0; j < 8; j++)
#pragma unroll
        for (int q = 0; q < 4; q++) cacc[j][q] = 0.f;

    for (int ch = 0; ch < 8; ch++) {
        cp_wait0();
        __syncthreads();
        if (ch < 7) LOADKV(vp, ch + 1, (ch + 1) & 1);
        const int st = ch & 1;
        const int krow = wid * 16 + (lane & 15);
#pragma unroll
        for (int j = 0; j < 8; j++) {
            unsigned b[2];
            ldm_x2_trans(b[0], b[1], &KV[st][krow][8 * j]);
            mma16816(cacc[j], aw[ch], b);
        }
    }
    __syncthreads();   // protect KV overlay before cpart writes

    // ---- phase 4: cross-warp reduce, write ctx fp16 ----
#pragma unroll
    for (int j = 0; j < 8; j++) {
        const int n = 8 * j + 2 * (lane & 3);
        const int r = lane >> 2;
        *(float2*)&cpart[wid][r][n] = make_float2(cacc[j][0], cacc[j][1]);
        *(float2*)&cpart[wid][r + 8][n] = make_float2(cacc[j][2], cacc[j][3]);
    }
    __syncthreads();
    {
        const int r = tid >> 4, d = (tid & 15) * 4;
        float4 s = make_float4(0.f, 0.f, 0.f, 0.f);
#pragma unroll
        for (int w = 0; w < 8; w++) {
            float4 v = *(const float4*)&cpart[w][r][d];
            s.x += v.x; s.y += v.y; s.z += v.z; s.w += v.w;
        }
        const int m = (bat << 10) + qb + r;
        const int h = bh & 15;
        __half2 h0 = __floats2half2_rn(s.x, s.y);
        __half2 h1 = __floats2half2_rn(s.z, s.w);
        uint2 o;
        o.x = *reinterpret_cast<unsigned*>(&h0);
        o.y = *reinterpret_cast<unsigned*>(&h1);
        *(uint2*)&g_ctxh[(size_t)m * 1024 + (h << 6) + d] = o;
    }
#undef LOADKV
}

// ---------------- LayerNorm(residual + g_tmp) -------------------------------
__global__ __launch_bounds__(256) void ln_kernel(const float* __restrict__ resid,
                                                 const float* __restrict__ gam,
                                                 const float* __restrict__ bet,
                                                 float* __restrict__ out)
{
    __shared__ float r1[256];
    __shared__ float r2[256];
    const int row = blockIdx.x;
    const int t = threadIdx.x;
    float4 x = *(const float4*)&g_tmp[((size_t)row << 10) + t * 4];
    float4 rr = *(const float4*)&resid[((size_t)row << 10) + t * 4];
    x.x += rr.x; x.y += rr.y; x.z += rr.z; x.w += rr.w;
    r1[t] = x.x + x.y + x.z + x.w;
    r2[t] = x.x * x.x + x.y * x.y + x.z * x.z + x.w * x.w;
    __syncthreads();
    for (int s = 128; s > 0; s >>= 1) {
        if (t < s) { r1[t] += r1[t + s]; r2[t] += r2[t + s]; }
        __syncthreads();
    }
    const float mu = r1[0] * (1.f / 1024.f);
    const float var = r2[0] * (1.f / 1024.f) - mu * mu;
    const float rs = rsqrtf(var + 1e-5f);
    float4 gv = *(const float4*)&gam[t * 4];
    float4 bv = *(const float4*)&bet[t * 4];
    float4 o;
    o.x = (x.x - mu) * rs * gv.x + bv.x;
    o.y = (x.y - mu) * rs * gv.y + bv.y;
    o.z = (x.z - mu) * rs * gv.z + bv.z;
    o.w = (x.w - mu) * rs * gv.w + bv.w;
    *(float4*)&out[((size_t)row << 10) + t * 4] = o;
}

// ---------------------------------------------------------------------------
extern "C" void kernel_launch(void* const* d_in, const int* in_sizes, int n_in,
                              void* d_out, int out_size)
{
    const float* Q = (const float*)d_in[0];
    const float* K = (const float*)d_in[1];
    const float* V = (const float*)d_in[2];
    const unsigned char* mask = (const unsigned char*)d_in[3];
    const float* bq = (const float*)d_in[5];
    const float* bk = (const float*)d_in[7];
    const float* bv = (const float*)d_in[9];
    const float* bout = (const float*)d_in[11];
    const float* ln_g = (const float*)d_in[12];
    const float* ln_b = (const float*)d_in[13];
    float* out = (float*)d_out;

    const long long OUT_ELEMS = 4LL * 1024 * 1024;
    const long long ATTN_ELEMS = 64LL * 1024 * 1024;
    float* attn;
    if ((long long)out_size >= OUT_ELEMS + ATTN_ELEMS) {
        attn = out + OUT_ELEMS;
    } else {
        void* p = nullptr;
        cudaGetSymbolAddress(&p, g_attn_fb);
        attn = (float*)p;
    }

    cvt_x3<<<dim3(4096, 3), 256>>>((const float4*)Q, (const float4*)K, (const float4*)V);
    cvt_wt4<<<dim3(32, 32, 4), dim3(32, 8)>>>((const float*)d_in[4], (const float*)d_in[6],
                                              (const float*)d_in[8], (const float*)d_in[10]);

    proj_h<<<dim3(8, 32, 3), 256>>>(bq, bk, bv, -1);

    attn_kernel<<<dim3(64, 64), 256>>>(mask, attn);

    proj_h<<<dim3(8, 32), 256>>>(bout, bout, bout, 3);
    ln_kernel<<<4096, 256>>>(Q, ln_g, ln_b, out);
}

// round 13
// speedup vs baseline: 1.5540x; 1.0216x over previous
#include <cuda_runtime.h>
#include <cuda_fp16.h>
#include <math.h>

#define B_ 4
#define S_ 1024
#define D_ 1024
#define H_ 16
#define BH 64
#define MROWS 4096

// ---------------- device scratch (no allocation allowed) -------------------
__device__ __half g_xh[3][MROWS * D_];
__device__ __half g_wt[4][D_ * D_];
__device__ __half g_qh[BH * S_ * 64];
__device__ __half g_kh[BH * S_ * 64];
__device__ __half g_vh[BH * S_ * 64];
__device__ __half g_ctxh[MROWS * D_];
__device__ float  g_tmp[MROWS * D_];
__device__ float  g_attn_fb[(size_t)BH * S_ * S_];

// ---------------- helpers ---------------------------------------------------
__device__ __forceinline__ void mma16816(float* c, const unsigned* a, const unsigned* b)
{
    asm volatile(
        "mma.sync.aligned.m16n8k16.row.col.f32.f16.f16.f32 "
        "{%0,%1,%2,%3}, {%4,%5,%6,%7}, {%8,%9}, {%0,%1,%2,%3};\n"
        : "+f"(c[0]), "+f"(c[1]), "+f"(c[2]), "+f"(c[3])
        : "r"(a[0]), "r"(a[1]), "r"(a[2]), "r"(a[3]), "r"(b[0]), "r"(b[1]));
}

__device__ __forceinline__ void cp_async16(void* smem, const void* gmem)
{
    unsigned s = (unsigned)__cvta_generic_to_shared(smem);
    asm volatile("cp.async.ca.shared.global [%0], [%1], 16;\n" :: "r"(s), "l"(gmem));
}
__device__ __forceinline__ void cp_commit() { asm volatile("cp.async.commit_group;\n"); }
__device__ __forceinline__ void cp_wait0() { asm volatile("cp.async.wait_group 0;\n"); }

__device__ __forceinline__ void ldm_x2_trans(unsigned& r0, unsigned& r1, const void* smem)
{
    unsigned s = (unsigned)__cvta_generic_to_shared(smem);
    asm volatile("ldmatrix.sync.aligned.m8n8.x2.trans.shared.b16 {%0,%1}, [%2];\n"
                 : "=r"(r0), "=r"(r1) : "r"(s));
}

// FMA-only exp. |rel err| < 2e-5 on our range.
__device__ __forceinline__ float fexp(float x)
{
    x = fmaxf(x, -87.0f);
    float t = x * 1.4426950408889634f;
    float fi = floorf(t);
    float f = t - fi;
    int i = (int)fi;
    float p = 1.5403530e-4f;
    p = fmaf(p, f, 1.3333558e-3f);
    p = fmaf(p, f, 9.6181291e-3f);
    p = fmaf(p, f, 5.5504109e-2f);
    p = fmaf(p, f, 2.4022651e-1f);
    p = fmaf(p, f, 6.9314718e-1f);
    p = fmaf(p, f, 1.0f);
    return __int_as_float((i + 127) << 23) * p;
}

// ---------------- converts (merged) -----------------------------------------
__global__ __launch_bounds__(256) void cvt_x3(const float4* __restrict__ Q,
                                              const float4* __restrict__ K,
                                              const float4* __restrict__ V)
{
    const int z = blockIdx.y;
    const float4* src = (z == 0) ? Q : (z == 1) ? K : V;
    __half* dst = g_xh[z];
    int i = blockIdx.x * 256 + threadIdx.x;
    float4 v = src[i];
    __half2 h0 = __floats2half2_rn(v.x, v.y);
    __half2 h1 = __floats2half2_rn(v.z, v.w);
    uint2 o;
    o.x = *reinterpret_cast<unsigned*>(&h0);
    o.y = *reinterpret_cast<unsigned*>(&h1);
    *reinterpret_cast<uint2*>(dst + 4 * (size_t)i) = o;
}

__global__ void cvt_wt4(const float* __restrict__ W0, const float* __restrict__ W1,
                        const float* __restrict__ W2, const float* __restrict__ W3)
{
    __shared__ float t[32][33];
    const int z = blockIdx.z;
    const float* W = (z == 0) ? W0 : (z == 1) ? W1 : (z == 2) ? W2 : W3;
    __half* Wt = g_wt[z];
    const int bx = blockIdx.x * 32;
    const int by = blockIdx.y * 32;
    const int tx = threadIdx.x, ty = threadIdx.y;
    for (int dy = 0; dy < 32; dy += 8)
        t[ty + dy][tx] = W[(size_t)(by + ty + dy) * 1024 + bx + tx];
    __syncthreads();
    for (int dy = 0; dy < 32; dy += 8)
        Wt[(size_t)(bx + ty + dy) * 1024 + by + tx] = __float2half_rn(t[tx][ty + dy]);
}

// ---------------- fp16 GEMM: cp.async 2-stage, single-sync loop -------------
__global__ __launch_bounds__(256) void proj_h(const float* __restrict__ b0,
                                              const float* __restrict__ b1,
                                              const float* __restrict__ b2, int mode)
{
    __shared__ __align__(16) __half As[2][128][40];
    __shared__ __align__(16) __half Bs[2][128][40];
    const int z = (mode < 0) ? blockIdx.z : 3;
    const __half* A = (z == 3) ? g_ctxh : g_xh[z];
    const __half* Bt = g_wt[z];
    const float* bias = (z == 1) ? b1 : (z == 2) ? b2 : b0;

    const int bm = blockIdx.y * 128, bn = blockIdx.x * 128;
    const int tid = threadIdx.x, lane = tid & 31, wid = tid >> 5;
    const int wm = (wid >> 1) * 32, wn = (wid & 1) * 64;
    const int sr = tid >> 1, sc = (tid & 1) * 16;

    float acc[2][8][4];
#pragma unroll
    for (int i = 0; i < 2; i++)
#pragma unroll
        for (int j = 0; j < 8; j++)
#pragma unroll
            for (int q = 0; q < 4; q++) acc[i][j][q] = 0.f;

    const __half* arow = A + (size_t)(bm + sr) * 1024 + sc;
    const __half* brow = Bt + (size_t)(bn + sr) * 1024 + sc;

    cp_async16(&As[0][sr][sc], arow);
    cp_async16(&As[0][sr][sc + 8], arow + 8);
    cp_async16(&Bs[0][sr][sc], brow);
    cp_async16(&Bs[0][sr][sc + 8], brow + 8);
    cp_commit();

    for (int it = 0; it < 32; it++) {
        cp_wait0();
        __syncthreads();
        if (it + 1 < 32) {
            const int k0 = (it + 1) * 32;
            const int st2 = (it + 1) & 1;
            cp_async16(&As[st2][sr][sc], arow + k0);
            cp_async16(&As[st2][sr][sc + 8], arow + k0 + 8);
            cp_async16(&Bs[st2][sr][sc], brow + k0);
            cp_async16(&Bs[st2][sr][sc + 8], brow + k0 + 8);
            cp_commit();
        }
        const int st = it & 1;
#pragma unroll
        for (int ks = 0; ks < 32; ks += 16) {
            unsigned af[2][4], bf[8][2];
            const int c = ks + 2 * (lane & 3);
#pragma unroll
            for (int i = 0; i < 2; i++) {
                const int r = wm + 16 * i + (lane >> 2);
                af[i][0] = *(const unsigned*)&As[st][r][c];
                af[i][1] = *(const unsigned*)&As[st][r + 8][c];
                af[i][2] = *(const unsigned*)&As[st][r][c + 8];
                af[i][3] = *(const unsigned*)&As[st][r + 8][c + 8];
            }
#pragma unroll
            for (int j = 0; j < 8; j++) {
                const int n = wn + 8 * j + (lane >> 2);
                bf[j][0] = *(const unsigned*)&Bs[st][n][c];
                bf[j][1] = *(const unsigned*)&Bs[st][n][c + 8];
            }
#pragma unroll
            for (int i = 0; i < 2; i++)
#pragma unroll
                for (int j = 0; j < 8; j++)
                    mma16816(acc[i][j], af[i], bf[j]);
        }
    }

#pragma unroll
    for (int i = 0; i < 2; i++) {
        const int r0 = bm + wm + 16 * i + (lane >> 2);
#pragma unroll
        for (int j = 0; j < 8; j++) {
            const int n0 = bn + wn + 8 * j + 2 * (lane & 3);
            const float bb0 = bias[n0], bb1 = bias[n0 + 1];
            const float l0 = acc[i][j][0] + bb0, l1 = acc[i][j][1] + bb1;
            const float h0 = acc[i][j][2] + bb0, h1 = acc[i][j][3] + bb1;
            if (z == 3) {
                *(float2*)&g_tmp[(size_t)r0 * 1024 + n0] = make_float2(l0, l1);
                *(float2*)&g_tmp[(size_t)(r0 + 8) * 1024 + n0] = make_float2(h0, h1);
            } else {
                __half* dst = (z == 0) ? g_qh : (z == 1) ? g_kh : g_vh;
                const int bat = r0 >> 10, s = r0 & 1023, h = n0 >> 6, d = n0 & 63;
                __half2 lo = __floats2half2_rn(l0, l1);
                __half2 hi = __floats2half2_rn(h0, h1);
                *(__half2*)&dst[(((size_t)(bat * 16 + h) * 1024) + s) * 64 + d] = lo;
                *(__half2*)&dst[(((size_t)(bat * 16 + h) * 1024) + s + 8) * 64 + d] = hi;
            }
        }
    }
}

// ---------------- fused attention (R12 + af-hoist only) ---------------------
__global__ __launch_bounds__(256) void attn_kernel(const unsigned char* __restrict__ mask,
                                                   float* __restrict__ attn)
{
    __shared__ __align__(16) __half Aq[16][88];   // stride 88: conflict-free
    __shared__ __align__(16) __half KV[2][128][88];
    __shared__ float rsum[16][8];
    __shared__ float rinv[16];
    float (*cpart)[16][64] = (float(*)[16][64])KV;   // phase-4 overlay

    const int bh = blockIdx.y;
    const int qb = blockIdx.x * 16;
    const int tid = threadIdx.x, lane = tid & 31, wid = tid >> 5;
    const int bat = bh >> 4;

    const __half* qp = g_qh + (size_t)bh * 65536;
    const __half* kp = g_kh + (size_t)bh * 65536;
    const __half* vp = g_vh + (size_t)bh * 65536;

    {
        const int r = tid >> 4, c = (tid & 15) * 4;
        *(uint2*)&Aq[r][c] = *(const uint2*)&qp[(size_t)(qb + r) * 64 + c];
    }

    const int lr = tid >> 1, lc = (tid & 1) * 32;
#define LOADKV(PTR, CH, ST) { \
        const __half* s_ = (PTR) + (size_t)((CH) * 128 + lr) * 64 + lc; \
        cp_async16(&KV[ST][lr][lc], s_); \
        cp_async16(&KV[ST][lr][lc + 8], s_ + 8); \
        cp_async16(&KV[ST][lr][lc + 16], s_ + 16); \
        cp_async16(&KV[ST][lr][lc + 24], s_ + 24); \
        cp_commit(); }

    LOADKV(kp, 0, 0);
    __syncthreads();                     // Aq visible to all warps

    // ---- hoist Q A-fragments: loaded ONCE (16 LDS/warp total) ----
    unsigned af[4][4];
    {
        const int r = lane >> 2, q2 = 2 * (lane & 3);
#pragma unroll
        for (int k4 = 0; k4 < 4; k4++) {
            const int c = k4 * 16 + q2;
            af[k4][0] = *(const unsigned*)&Aq[r][c];
            af[k4][1] = *(const unsigned*)&Aq[r + 8][c];
            af[k4][2] = *(const unsigned*)&Aq[r][c + 8];
            af[k4][3] = *(const unsigned*)&Aq[r + 8][c + 8];
        }
    }

    // ---- phase 1: scores (K pipelined, bf LDS only) ----
    float p[16][4];
#pragma unroll
    for (int t = 0; t < 16; t++)
#pragma unroll
        for (int q = 0; q < 4; q++) p[t][q] = 0.f;

    for (int ch = 0; ch < 8; ch++) {
        cp_wait0();
        __syncthreads();
        if (ch < 7) LOADKV(kp, ch + 1, (ch + 1) & 1);
        const int st = ch & 1;
#pragma unroll
        for (int k4 = 0; k4 < 4; k4++) {
            const int c = k4 * 16 + 2 * (lane & 3);
#pragma unroll
            for (int j = 0; j < 2; j++) {
                const int n = wid * 16 + 8 * j + (lane >> 2);
                unsigned bf[2];
                bf[0] = *(const unsigned*)&KV[st][n][c];
                bf[1] = *(const unsigned*)&KV[st][n][c + 8];
                mma16816(p[2 * ch + j], af[k4], bf);
            }
        }
    }

    // ---- phase 2: mask + scale + exp + row sums ----
    const unsigned char* mb = mask + ((size_t)bat << 20);
    const int r0g = qb + (lane >> 2);
    float s0 = 0.f, s1 = 0.f;
#pragma unroll
    for (int t = 0; t < 16; t++) {
        const int col = (t >> 1) * 128 + wid * 16 + (t & 1) * 8 + 2 * (lane & 3);
        uchar2 m0 = *(const uchar2*)(mb + ((size_t)r0g << 10) + col);
        uchar2 m1 = *(const uchar2*)(mb + ((size_t)(r0g + 8) << 10) + col);
        float v0 = m0.x ? -1e9f : p[t][0] * 0.125f;
        float v1 = m0.y ? -1e9f : p[t][1] * 0.125f;
        float v2 = m1.x ? -1e9f : p[t][2] * 0.125f;
        float v3 = m1.y ? -1e9f : p[t][3] * 0.125f;
        v0 = fexp(v0); v1 = fexp(v1); v2 = fexp(v2); v3 = fexp(v3);
        p[t][0] = v0; p[t][1] = v1; p[t][2] = v2; p[t][3] = v3;
        s0 += v0 + v1; s1 += v2 + v3;
    }
    s0 += __shfl_xor_sync(0xffffffffu, s0, 1);
    s0 += __shfl_xor_sync(0xffffffffu, s0, 2);
    s1 += __shfl_xor_sync(0xffffffffu, s1, 1);
    s1 += __shfl_xor_sync(0xffffffffu, s1, 2);
    if ((lane & 3) == 0) {
        rsum[lane >> 2][wid] = s0;
        rsum[8 + (lane >> 2)][wid] = s1;
    }
    __syncthreads();

    LOADKV(vp, 0, 0);   // prefetch V chunk 0 during normalization

    if (tid < 16) {
        float t = 0.f;
#pragma unroll
        for (int w = 0; w < 8; w++) t += rsum[tid][w];
        rinv[tid] = 1.f / t;
    }
    __syncthreads();
    const float inv0 = rinv[lane >> 2], inv1 = rinv[8 + (lane >> 2)];

    // ---- phase 2b: normalize, stream attn, pack fp16 A-frags ----
    float* ab = attn + ((size_t)bh << 20);
    unsigned aw[8][4];
#pragma unroll
    for (int ch = 0; ch < 8; ch++) {
#pragma unroll
        for (int j = 0; j < 2; j++) {
            const int t = 2 * ch + j;
            const float n0 = p[t][0] * inv0, n1 = p[t][1] * inv0;
            const float n2 = p[t][2] * inv1, n3 = p[t][3] * inv1;
            const int col = ch * 128 + wid * 16 + j * 8 + 2 * (lane & 3);
            __stcs((float2*)&ab[((size_t)r0g << 10) + col], make_float2(n0, n1));
            __stcs((float2*)&ab[((size_t)(r0g + 8) << 10) + col], make_float2(n2, n3));
            __half2 x0 = __floats2half2_rn(n0, n1);
            __half2 x1 = __floats2half2_rn(n2, n3);
            aw[ch][2 * j + 0] = *reinterpret_cast<unsigned*>(&x0);
            aw[ch][2 * j + 1] = *reinterpret_cast<unsigned*>(&x1);
        }
    }

    // ---- phase 3: ctx = attn @ V (ldmatrix.trans B-frags) ----
    float cacc[8][4];
#pragma unroll
    for (int j = 0; j < 8; j++)
#pragma unroll
        for (int q = 0; q < 4; q++) cacc[j][q] = 0.f;

    for (int ch = 0; ch < 8; ch++) {
        cp_wait0();
        __syncthreads();
        if (ch < 7) LOADKV(vp, ch + 1, (ch + 1) & 1);
        const int st = ch & 1;
        const int krow = wid * 16 + (lane & 15);
#pragma unroll
        for (int j = 0; j < 8; j++) {
            unsigned b[2];
            ldm_x2_trans(b[0], b[1], &KV[st][krow][8 * j]);
            mma16816(cacc[j], aw[ch], b);
        }
    }
    __syncthreads();   // protect KV overlay before cpart writes

    // ---- phase 4: cross-warp reduce, write ctx fp16 ----
#pragma unroll
    for (int j = 0; j < 8; j++) {
        const int n = 8 * j + 2 * (lane & 3);
        const int r = lane >> 2;
        *(float2*)&cpart[wid][r][n] = make_float2(cacc[j][0], cacc[j][1]);
        *(float2*)&cpart[wid][r + 8][n] = make_float2(cacc[j][2], cacc[j][3]);
    }
    __syncthreads();
    {
        const int r = tid >> 4, d = (tid & 15) * 4;
        float4 s = make_float4(0.f, 0.f, 0.f, 0.f);
#pragma unroll
        for (int w = 0; w < 8; w++) {
            float4 v = *(const float4*)&cpart[w][r][d];
            s.x += v.x; s.y += v.y; s.z += v.z; s.w += v.w;
        }
        const int m = (bat << 10) + qb + r;
        const int h = bh & 15;
        __half2 h0 = __floats2half2_rn(s.x, s.y);
        __half2 h1 = __floats2half2_rn(s.z, s.w);
        uint2 o;
        o.x = *reinterpret_cast<unsigned*>(&h0);
        o.y = *reinterpret_cast<unsigned*>(&h1);
        *(uint2*)&g_ctxh[(size_t)m * 1024 + (h << 6) + d] = o;
    }
#undef LOADKV
}

// ---------------- LayerNorm(residual + g_tmp) -------------------------------
__global__ __launch_bounds__(256) void ln_kernel(const float* __restrict__ resid,
                                                 const float* __restrict__ gam,
                                                 const float* __restrict__ bet,
                                                 float* __restrict__ out)
{
    __shared__ float r1[256];
    __shared__ float r2[256];
    const int row = blockIdx.x;
    const int t = threadIdx.x;
    float4 x = *(const float4*)&g_tmp[((size_t)row << 10) + t * 4];
    float4 rr = *(const float4*)&resid[((size_t)row << 10) + t * 4];
    x.x += rr.x; x.y += rr.y; x.z += rr.z; x.w += rr.w;
    r1[t] = x.x + x.y + x.z + x.w;
    r2[t] = x.x * x.x + x.y * x.y + x.z * x.z + x.w * x.w;
    __syncthreads();
    for (int s = 128; s > 0; s >>= 1) {
        if (t < s) { r1[t] += r1[t + s]; r2[t] += r2[t + s]; }
        __syncthreads();
    }
    const float mu = r1[0] * (1.f / 1024.f);
    const float var = r2[0] * (1.f / 1024.f) - mu * mu;
    const float rs = rsqrtf(var + 1e-5f);
    float4 gv = *(const float4*)&gam[t * 4];
    float4 bv = *(const float4*)&bet[t * 4];
    float4 o;
    o.x = (x.x - mu) * rs * gv.x + bv.x;
    o.y = (x.y - mu) * rs * gv.y + bv.y;
    o.z = (x.z - mu) * rs * gv.z + bv.z;
    o.w = (x.w - mu) * rs * gv.w + bv.w;
    *(float4*)&out[((size_t)row << 10) + t * 4] = o;
}

// ---------------------------------------------------------------------------
extern "C" void kernel_launch(void* const* d_in, const int* in_sizes, int n_in,
                              void* d_out, int out_size)
{
    const float* Q = (const float*)d_in[0];
    const float* K = (const float*)d_in[1];
    const float* V = (const float*)d_in[2];
    const unsigned char* mask = (const unsigned char*)d_in[3];
    const float* bq = (const float*)d_in[5];
    const float* bk = (const float*)d_in[7];
    const float* bv = (const float*)d_in[9];
    const float* bout = (const float*)d_in[11];
    const float* ln_g = (const float*)d_in[12];
    const float* ln_b = (const float*)d_in[13];
    float* out = (float*)d_out;

    const long long OUT_ELEMS = 4LL * 1024 * 1024;
    const long long ATTN_ELEMS = 64LL * 1024 * 1024;
    float* attn;
    if ((long long)out_size >= OUT_ELEMS + ATTN_ELEMS) {
        attn = out + OUT_ELEMS;
    } else {
        void* p = nullptr;
        cudaGetSymbolAddress(&p, g_attn_fb);
        attn = (float*)p;
    }

    cvt_x3<<<dim3(4096, 3), 256>>>((const float4*)Q, (const float4*)K, (const float4*)V);
    cvt_wt4<<<dim3(32, 32, 4), dim3(32, 8)>>>((const float*)d_in[4], (const float*)d_in[6],
                                              (const float*)d_in[8], (const float*)d_in[10]);

    proj_h<<<dim3(8, 32, 3), 256>>>(bq, bk, bv, -1);

    attn_kernel<<<dim3(64, 64), 256>>>(mask, attn);

    proj_h<<<dim3(8, 32), 256>>>(bout, bout, bout, 3);
    ln_kernel<<<4096, 256>>>(Q, ln_g, ln_b, out);
}

// round 14
// speedup vs baseline: 1.5667x; 1.0081x over previous
#include <cuda_runtime.h>
#include <cuda_fp16.h>
#include <math.h>

#define B_ 4
#define S_ 1024
#define D_ 1024
#define H_ 16
#define BH 64
#define MROWS 4096

// ---------------- device scratch (no allocation allowed) -------------------
__device__ __half g_xh[3][MROWS * D_];
__device__ __half g_wt[4][D_ * D_];
__device__ __half g_qh[BH * S_ * 64];
__device__ __half g_kh[BH * S_ * 64];
__device__ __half g_vh[BH * S_ * 64];
__device__ __half g_ctxh[MROWS * D_];
__device__ float  g_tmp[MROWS * D_];
__device__ float  g_attn_fb[(size_t)BH * S_ * S_];

// ---------------- helpers ---------------------------------------------------
__device__ __forceinline__ void mma16816(float* c, const unsigned* a, const unsigned* b)
{
    asm volatile(
        "mma.sync.aligned.m16n8k16.row.col.f32.f16.f16.f32 "
        "{%0,%1,%2,%3}, {%4,%5,%6,%7}, {%8,%9}, {%0,%1,%2,%3};\n"
        : "+f"(c[0]), "+f"(c[1]), "+f"(c[2]), "+f"(c[3])
        : "r"(a[0]), "r"(a[1]), "r"(a[2]), "r"(a[3]), "r"(b[0]), "r"(b[1]));
}

__device__ __forceinline__ void cp_async16(void* smem, const void* gmem)
{
    unsigned s = (unsigned)__cvta_generic_to_shared(smem);
    asm volatile("cp.async.ca.shared.global [%0], [%1], 16;\n" :: "r"(s), "l"(gmem));
}
__device__ __forceinline__ void cp_commit() { asm volatile("cp.async.commit_group;\n"); }
__device__ __forceinline__ void cp_wait0() { asm volatile("cp.async.wait_group 0;\n"); }

__device__ __forceinline__ void ldm_x2_trans(unsigned& r0, unsigned& r1, const void* smem)
{
    unsigned s = (unsigned)__cvta_generic_to_shared(smem);
    asm volatile("ldmatrix.sync.aligned.m8n8.x2.trans.shared.b16 {%0,%1}, [%2];\n"
                 : "=r"(r0), "=r"(r1) : "r"(s));
}

// FMA-only exp. |rel err| < 2e-5 on our range.
__device__ __forceinline__ float fexp(float x)
{
    x = fmaxf(x, -87.0f);
    float t = x * 1.4426950408889634f;
    float fi = floorf(t);
    float f = t - fi;
    int i = (int)fi;
    float p = 1.5403530e-4f;
    p = fmaf(p, f, 1.3333558e-3f);
    p = fmaf(p, f, 9.6181291e-3f);
    p = fmaf(p, f, 5.5504109e-2f);
    p = fmaf(p, f, 2.4022651e-1f);
    p = fmaf(p, f, 6.9314718e-1f);
    p = fmaf(p, f, 1.0f);
    return __int_as_float((i + 127) << 23) * p;
}

// ---------------- converts (merged) -----------------------------------------
__global__ __launch_bounds__(256) void cvt_x3(const float4* __restrict__ Q,
                                              const float4* __restrict__ K,
                                              const float4* __restrict__ V)
{
    const int z = blockIdx.y;
    const float4* src = (z == 0) ? Q : (z == 1) ? K : V;
    __half* dst = g_xh[z];
    int i = blockIdx.x * 256 + threadIdx.x;
    float4 v = src[i];
    __half2 h0 = __floats2half2_rn(v.x, v.y);
    __half2 h1 = __floats2half2_rn(v.z, v.w);
    uint2 o;
    o.x = *reinterpret_cast<unsigned*>(&h0);
    o.y = *reinterpret_cast<unsigned*>(&h1);
    *reinterpret_cast<uint2*>(dst + 4 * (size_t)i) = o;
}

__global__ void cvt_wt4(const float* __restrict__ W0, const float* __restrict__ W1,
                        const float* __restrict__ W2, const float* __restrict__ W3)
{
    __shared__ float t[32][33];
    const int z = blockIdx.z;
    const float* W = (z == 0) ? W0 : (z == 1) ? W1 : (z == 2) ? W2 : W3;
    __half* Wt = g_wt[z];
    const int bx = blockIdx.x * 32;
    const int by = blockIdx.y * 32;
    const int tx = threadIdx.x, ty = threadIdx.y;
    for (int dy = 0; dy < 32; dy += 8)
        t[ty + dy][tx] = W[(size_t)(by + ty + dy) * 1024 + bx + tx];
    __syncthreads();
    for (int dy = 0; dy < 32; dy += 8)
        Wt[(size_t)(bx + ty + dy) * 1024 + by + tx] = __float2half_rn(t[tx][ty + dy]);
}

// ---------------- fp16 GEMM: cp.async 2-stage, k-chunk 64 -------------------
__global__ __launch_bounds__(256) void proj_h(const float* __restrict__ b0,
                                              const float* __restrict__ b1,
                                              const float* __restrict__ b2, int mode)
{
    __shared__ __align__(16) __half As[2][128][72];
    __shared__ __align__(16) __half Bs[2][128][72];
    const int z = (mode < 0) ? blockIdx.z : 3;
    const __half* A = (z == 3) ? g_ctxh : g_xh[z];
    const __half* Bt = g_wt[z];
    const float* bias = (z == 1) ? b1 : (z == 2) ? b2 : b0;

    const int bm = blockIdx.y * 128, bn = blockIdx.x * 128;
    const int tid = threadIdx.x, lane = tid & 31, wid = tid >> 5;
    const int wm = (wid >> 1) * 32, wn = (wid & 1) * 64;
    const int sr = tid >> 1, sc = (tid & 1) * 32;

    float acc[2][8][4];
#pragma unroll
    for (int i = 0; i < 2; i++)
#pragma unroll
        for (int j = 0; j < 8; j++)
#pragma unroll
            for (int q = 0; q < 4; q++) acc[i][j][q] = 0.f;

    const __half* arow = A + (size_t)(bm + sr) * 1024 + sc;
    const __half* brow = Bt + (size_t)(bn + sr) * 1024 + sc;

#define LD_STAGE(ST, K0) { \
        cp_async16(&As[ST][sr][sc],      arow + (K0)); \
        cp_async16(&As[ST][sr][sc + 8],  arow + (K0) + 8); \
        cp_async16(&As[ST][sr][sc + 16], arow + (K0) + 16); \
        cp_async16(&As[ST][sr][sc + 24], arow + (K0) + 24); \
        cp_async16(&Bs[ST][sr][sc],      brow + (K0)); \
        cp_async16(&Bs[ST][sr][sc + 8],  brow + (K0) + 8); \
        cp_async16(&Bs[ST][sr][sc + 16], brow + (K0) + 16); \
        cp_async16(&Bs[ST][sr][sc + 24], brow + (K0) + 24); \
        cp_commit(); }

    LD_STAGE(0, 0);

    for (int it = 0; it < 16; it++) {
        cp_wait0();
        __syncthreads();
        if (it + 1 < 16) LD_STAGE((it + 1) & 1, (it + 1) * 64);
        const int st = it & 1;
#pragma unroll
        for (int ks = 0; ks < 64; ks += 16) {
            unsigned af[2][4], bf[8][2];
            const int c = ks + 2 * (lane & 3);
#pragma unroll
            for (int i = 0; i < 2; i++) {
                const int r = wm + 16 * i + (lane >> 2);
                af[i][0] = *(const unsigned*)&As[st][r][c];
                af[i][1] = *(const unsigned*)&As[st][r + 8][c];
                af[i][2] = *(const unsigned*)&As[st][r][c + 8];
                af[i][3] = *(const unsigned*)&As[st][r + 8][c + 8];
            }
#pragma unroll
            for (int j = 0; j < 8; j++) {
                const int n = wn + 8 * j + (lane >> 2);
                bf[j][0] = *(const unsigned*)&Bs[st][n][c];
                bf[j][1] = *(const unsigned*)&Bs[st][n][c + 8];
            }
#pragma unroll
            for (int i = 0; i < 2; i++)
#pragma unroll
                for (int j = 0; j < 8; j++)
                    mma16816(acc[i][j], af[i], bf[j]);
        }
    }
#undef LD_STAGE

#pragma unroll
    for (int i = 0; i < 2; i++) {
        const int r0 = bm + wm + 16 * i + (lane >> 2);
#pragma unroll
        for (int j = 0; j < 8; j++) {
            const int n0 = bn + wn + 8 * j + 2 * (lane & 3);
            const float bb0 = bias[n0], bb1 = bias[n0 + 1];
            const float l0 = acc[i][j][0] + bb0, l1 = acc[i][j][1] + bb1;
            const float h0 = acc[i][j][2] + bb0, h1 = acc[i][j][3] + bb1;
            if (z == 3) {
                *(float2*)&g_tmp[(size_t)r0 * 1024 + n0] = make_float2(l0, l1);
                *(float2*)&g_tmp[(size_t)(r0 + 8) * 1024 + n0] = make_float2(h0, h1);
            } else {
                __half* dst = (z == 0) ? g_qh : (z == 1) ? g_kh : g_vh;
                const int bat = r0 >> 10, s = r0 & 1023, h = n0 >> 6, d = n0 & 63;
                __half2 lo = __floats2half2_rn(l0, l1);
                __half2 hi = __floats2half2_rn(h0, h1);
                *(__half2*)&dst[(((size_t)(bat * 16 + h) * 1024) + s) * 64 + d] = lo;
                *(__half2*)&dst[(((size_t)(bat * 16 + h) * 1024) + s + 8) * 64 + d] = hi;
            }
        }
    }
}

// ---------------- fused attention (identical to R13 winner) -----------------
__global__ __launch_bounds__(256) void attn_kernel(const unsigned char* __restrict__ mask,
                                                   float* __restrict__ attn)
{
    __shared__ __align__(16) __half Aq[16][88];
    __shared__ __align__(16) __half KV[2][128][88];
    __shared__ float rsum[16][8];
    __shared__ float rinv[16];
    float (*cpart)[16][64] = (float(*)[16][64])KV;   // phase-4 overlay

    const int bh = blockIdx.y;
    const int qb = blockIdx.x * 16;
    const int tid = threadIdx.x, lane = tid & 31, wid = tid >> 5;
    const int bat = bh >> 4;

    const __half* qp = g_qh + (size_t)bh * 65536;
    const __half* kp = g_kh + (size_t)bh * 65536;
    const __half* vp = g_vh + (size_t)bh * 65536;

    {
        const int r = tid >> 4, c = (tid & 15) * 4;
        *(uint2*)&Aq[r][c] = *(const uint2*)&qp[(size_t)(qb + r) * 64 + c];
    }

    const int lr = tid >> 1, lc = (tid & 1) * 32;
#define LOADKV(PTR, CH, ST) { \
        const __half* s_ = (PTR) + (size_t)((CH) * 128 + lr) * 64 + lc; \
        cp_async16(&KV[ST][lr][lc], s_); \
        cp_async16(&KV[ST][lr][lc + 8], s_ + 8); \
        cp_async16(&KV[ST][lr][lc + 16], s_ + 16); \
        cp_async16(&KV[ST][lr][lc + 24], s_ + 24); \
        cp_commit(); }

    LOADKV(kp, 0, 0);
    __syncthreads();                     // Aq visible to all warps

    // ---- hoist Q A-fragments: loaded ONCE ----
    unsigned af[4][4];
    {
        const int r = lane >> 2, q2 = 2 * (lane & 3);
#pragma unroll
        for (int k4 = 0; k4 < 4; k4++) {
            const int c = k4 * 16 + q2;
            af[k4][0] = *(const unsigned*)&Aq[r][c];
            af[k4][1] = *(const unsigned*)&Aq[r + 8][c];
            af[k4][2] = *(const unsigned*)&Aq[r][c + 8];
            af[k4][3] = *(const unsigned*)&Aq[r + 8][c + 8];
        }
    }

    // ---- phase 1: scores (K pipelined, bf LDS only) ----
    float p[16][4];
#pragma unroll
    for (int t = 0; t < 16; t++)
#pragma unroll
        for (int q = 0; q < 4; q++) p[t][q] = 0.f;

    for (int ch = 0; ch < 8; ch++) {
        cp_wait0();
        __syncthreads();
        if (ch < 7) LOADKV(kp, ch + 1, (ch + 1) & 1);
        const int st = ch & 1;
#pragma unroll
        for (int k4 = 0; k4 < 4; k4++) {
            const int c = k4 * 16 + 2 * (lane & 3);
#pragma unroll
            for (int j = 0; j < 2; j++) {
                const int n = wid * 16 + 8 * j + (lane >> 2);
                unsigned bf[2];
                bf[0] = *(const unsigned*)&KV[st][n][c];
                bf[1] = *(const unsigned*)&KV[st][n][c + 8];
                mma16816(p[2 * ch + j], af[k4], bf);
            }
        }
    }

    // ---- phase 2: mask + scale + exp + row sums ----
    const unsigned char* mb = mask + ((size_t)bat << 20);
    const int r0g = qb + (lane >> 2);
    float s0 = 0.f, s1 = 0.f;
#pragma unroll
    for (int t = 0; t < 16; t++) {
        const int col = (t >> 1) * 128 + wid * 16 + (t & 1) * 8 + 2 * (lane & 3);
        uchar2 m0 = *(const uchar2*)(mb + ((size_t)r0g << 10) + col);
        uchar2 m1 = *(const uchar2*)(mb + ((size_t)(r0g + 8) << 10) + col);
        float v0 = m0.x ? -1e9f : p[t][0] * 0.125f;
        float v1 = m0.y ? -1e9f : p[t][1] * 0.125f;
        float v2 = m1.x ? -1e9f : p[t][2] * 0.125f;
        float v3 = m1.y ? -1e9f : p[t][3] * 0.125f;
        v0 = fexp(v0); v1 = fexp(v1); v2 = fexp(v2); v3 = fexp(v3);
        p[t][0] = v0; p[t][1] = v1; p[t][2] = v2; p[t][3] = v3;
        s0 += v0 + v1; s1 += v2 + v3;
    }
    s0 += __shfl_xor_sync(0xffffffffu, s0, 1);
    s0 += __shfl_xor_sync(0xffffffffu, s0, 2);
    s1 += __shfl_xor_sync(0xffffffffu, s1, 1);
    s1 += __shfl_xor_sync(0xffffffffu, s1, 2);
    if ((lane & 3) == 0) {
        rsum[lane >> 2][wid] = s0;
        rsum[8 + (lane >> 2)][wid] = s1;
    }
    __syncthreads();

    LOADKV(vp, 0, 0);   // prefetch V chunk 0 during normalization

    if (tid < 16) {
        float t = 0.f;
#pragma unroll
        for (int w = 0; w < 8; w++) t += rsum[tid][w];
        rinv[tid] = 1.f / t;
    }
    __syncthreads();
    const float inv0 = rinv[lane >> 2], inv1 = rinv[8 + (lane >> 2)];

    // ---- phase 2b: normalize, stream attn, pack fp16 A-frags ----
    float* ab = attn + ((size_t)bh << 20);
    unsigned aw[8][4];
#pragma unroll
    for (int ch = 0; ch < 8; ch++) {
#pragma unroll
        for (int j = 0; j < 2; j++) {
            const int t = 2 * ch + j;
            const float n0 = p[t][0] * inv0, n1 = p[t][1] * inv0;
            const float n2 = p[t][2] * inv1, n3 = p[t][3] * inv1;
            const int col = ch * 128 + wid * 16 + j * 8 + 2 * (lane & 3);
            __stcs((float2*)&ab[((size_t)r0g << 10) + col], make_float2(n0, n1));
            __stcs((float2*)&ab[((size_t)(r0g + 8) << 10) + col], make_float2(n2, n3));
            __half2 x0 = __floats2half2_rn(n0, n1);
            __half2 x1 = __floats2half2_rn(n2, n3);
            aw[ch][2 * j + 0] = *reinterpret_cast<unsigned*>(&x0);
            aw[ch][2 * j + 1] = *reinterpret_cast<unsigned*>(&x1);
        }
    }

    // ---- phase 3: ctx = attn @ V (ldmatrix.trans B-frags) ----
    float cacc[8][4];
#pragma unroll
    for (int j = 0; j < 8; j++)
#pragma unroll
        for (int q = 0; q < 4; q++) cacc[j][q] = 0.f;

    for (int ch = 0; ch < 8; ch++) {
        cp_wait0();
        __syncthreads();
        if (ch < 7) LOADKV(vp, ch + 1, (ch + 1) & 1);
        const int st = ch & 1;
        const int krow = wid * 16 + (lane & 15);
#pragma unroll
        for (int j = 0; j < 8; j++) {
            unsigned b[2];
            ldm_x2_trans(b[0], b[1], &KV[st][krow][8 * j]);
            mma16816(cacc[j], aw[ch], b);
        }
    }
    __syncthreads();   // protect KV overlay before cpart writes

    // ---- phase 4: cross-warp reduce, write ctx fp16 ----
#pragma unroll
    for (int j = 0; j < 8; j++) {
        const int n = 8 * j + 2 * (lane & 3);
        const int r = lane >> 2;
        *(float2*)&cpart[wid][r][n] = make_float2(cacc[j][0], cacc[j][1]);
        *(float2*)&cpart[wid][r + 8][n] = make_float2(cacc[j][2], cacc[j][3]);
    }
    __syncthreads();
    {
        const int r = tid >> 4, d = (tid & 15) * 4;
        float4 s = make_float4(0.f, 0.f, 0.f, 0.f);
#pragma unroll
        for (int w = 0; w < 8; w++) {
            float4 v = *(const float4*)&cpart[w][r][d];
            s.x += v.x; s.y += v.y; s.z += v.z; s.w += v.w;
        }
        const int m = (bat << 10) + qb + r;
        const int h = bh & 15;
        __half2 h0 = __floats2half2_rn(s.x, s.y);
        __half2 h1 = __floats2half2_rn(s.z, s.w);
        uint2 o;
        o.x = *reinterpret_cast<unsigned*>(&h0);
        o.y = *reinterpret_cast<unsigned*>(&h1);
        *(uint2*)&g_ctxh[(size_t)m * 1024 + (h << 6) + d] = o;
    }
#undef LOADKV
}

// ---------------- LayerNorm(residual + g_tmp) -------------------------------
__global__ __launch_bounds__(256) void ln_kernel(const float* __restrict__ resid,
                                                 const float* __restrict__ gam,
                                                 const float* __restrict__ bet,
                                                 float* __restrict__ out)
{
    __shared__ float r1[256];
    __shared__ float r2[256];
    const int row = blockIdx.x;
    const int t = threadIdx.x;
    float4 x = *(const float4*)&g_tmp[((size_t)row << 10) + t * 4];
    float4 rr = *(const float4*)&resid[((size_t)row << 10) + t * 4];
    x.x += rr.x; x.y += rr.y; x.z += rr.z; x.w += rr.w;
    r1[t] = x.x + x.y + x.z + x.w;
    r2[t] = x.x * x.x + x.y * x.y + x.z * x.z + x.w * x.w;
    __syncthreads();
    for (int s = 128; s > 0; s >>= 1) {
        if (t < s) { r1[t] += r1[t + s]; r2[t] += r2[t + s]; }
        __syncthreads();
    }
    const float mu = r1[0] * (1.f / 1024.f);
    const float var = r2[0] * (1.f / 1024.f) - mu * mu;
    const float rs = rsqrtf(var + 1e-5f);
    float4 gv = *(const float4*)&gam[t * 4];
    float4 bv = *(const float4*)&bet[t * 4];
    float4 o;
    o.x = (x.x - mu) * rs * gv.x + bv.x;
    o.y = (x.y - mu) * rs * gv.y + bv.y;
    o.z = (x.z - mu) * rs * gv.z + bv.z;
    o.w = (x.w - mu) * rs * gv.w + bv.w;
    *(float4*)&out[((size_t)row << 10) + t * 4] = o;
}

// ---------------------------------------------------------------------------
extern "C" void kernel_launch(void* const* d_in, const int* in_sizes, int n_in,
                              void* d_out, int out_size)
{
    const float* Q = (const float*)d_in[0];
    const float* K = (const float*)d_in[1];
    const float* V = (const float*)d_in[2];
    const unsigned char* mask = (const unsigned char*)d_in[3];
    const float* bq = (const float*)d_in[5];
    const float* bk = (const float*)d_in[7];
    const float* bv = (const float*)d_in[9];
    const float* bout = (const float*)d_in[11];
    const float* ln_g = (const float*)d_in[12];
    const float* ln_b = (const float*)d_in[13];
    float* out = (float*)d_out;

    const long long OUT_ELEMS = 4LL * 1024 * 1024;
    const long long ATTN_ELEMS = 64LL * 1024 * 1024;
    float* attn;
    if ((long long)out_size >= OUT_ELEMS + ATTN_ELEMS) {
        attn = out + OUT_ELEMS;
    } else {
        void* p = nullptr;
        cudaGetSymbolAddress(&p, g_attn_fb);
        attn = (float*)p;
    }

    cvt_x3<<<dim3(4096, 3), 256>>>((const float4*)Q, (const float4*)K, (const float4*)V);
    cvt_wt4<<<dim3(32, 32, 4), dim3(32, 8)>>>((const float*)d_in[4], (const float*)d_in[6],
                                              (const float*)d_in[8], (const float*)d_in[10]);

    proj_h<<<dim3(8, 32, 3), 256>>>(bq, bk, bv, -1);

    attn_kernel<<<dim3(64, 64), 256>>>(mask, attn);

    proj_h<<<dim3(8, 32), 256>>>(bout, bout, bout, 3);
    ln_kernel<<<4096, 256>>>(Q, ln_g, ln_b, out);
}